// round 8
// baseline (speedup 1.0000x reference)
#include <cuda_runtime.h>
#include <cstdint>

#define NPTS 1048576
#define HD 32
#define NB 4
#define TPB 128

typedef unsigned long long u64;

// ---- packed f32x2 helpers (Blackwell) ----
__device__ __forceinline__ u64 splat2(float w) {
    u64 r; asm("mov.b64 %0, {%1, %1};" : "=l"(r) : "f"(w)); return r;
}
__device__ __forceinline__ u64 ffma2(u64 a, u64 b, u64 c) {
    u64 d; asm("fma.rn.f32x2 %0, %1, %2, %3;" : "=l"(d) : "l"(a), "l"(b), "l"(c));
    return d;
}
__device__ __forceinline__ void unpk2(u64 v, float& a, float& b) {
    asm("mov.b64 {%0, %1}, %2;" : "=f"(a), "=f"(b) : "l"(v));
}
// LDS.128 returning two 64-bit lanes == two pre-packed f32x2 weight pairs
__device__ __forceinline__ void lds128(u64& a, u64& b, uint32_t addr) {
    asm volatile("ld.shared.v2.u64 {%0, %1}, [%2];" : "=l"(a), "=l"(b) : "r"(addr));
}
__device__ __forceinline__ void lds128f(float& a, float& b, float& c, float& d, uint32_t addr) {
    asm volatile("ld.shared.v4.f32 {%0, %1, %2, %3}, [%4];"
                 : "=f"(a), "=f"(b), "=f"(c), "=f"(d) : "r"(addr));
}
__device__ __forceinline__ u64 lds64(uint32_t addr) {
    u64 a; asm volatile("ld.shared.u64 %0, [%1];" : "=l"(a) : "r"(addr));
    return a;
}
__device__ __forceinline__ float tanh_fast(float x) {
    float y; asm("tanh.approx.f32 %0, %1;" : "=f"(y) : "f"(x));
    return y;
}

// 3 CTAs/SM (reg cap 170): 12 warps = 3/SMSP. Live state trimmed (~150 regs)
// so ptxas can prefetch LDS without spilling.
__global__ __launch_bounds__(TPB, 3)
void pfnn_kernel(const float* __restrict__ x,
                 const float* __restrict__ W0, const float* __restrict__ b0,
                 const float* __restrict__ W1, const float* __restrict__ b1,
                 const float* __restrict__ W2, const float* __restrict__ b2,
                 const float* __restrict__ W3, const float* __restrict__ b3,
                 float* __restrict__ out) {
    // Weights in ORIGINAL [b][d][j] layout (j contiguous): each LDS.128 over j
    // yields two ready f32x2 weight pairs, each feeding FFMA2 for TWO points
    // -> 4 FFMA2 per LDS.128.
    __shared__ __align__(16) float sW0[NB * 3 * HD];
    __shared__ __align__(16) float sB0[NB * HD];
    __shared__ __align__(16) float sW1[NB * HD * HD];
    __shared__ __align__(16) float sB1[NB * HD];
    __shared__ __align__(16) float sW2[NB * HD * HD];
    __shared__ __align__(16) float sB2[NB * HD];
    __shared__ __align__(16) float sW3[NB * HD];
    __shared__ __align__(16) float sB3[NB];

    for (int i = threadIdx.x; i < NB * 3 * HD; i += TPB) sW0[i] = W0[i];
    for (int i = threadIdx.x; i < NB * HD; i += TPB) {
        sB0[i] = b0[i];
        sB1[i] = b1[i];
        sB2[i] = b2[i];
        sW3[i] = W3[i];   // [B,H,1] -> flat [B][H]
    }
    for (int i = threadIdx.x; i < NB * HD * HD; i += TPB) {
        sW1[i] = W1[i];
        sW2[i] = W2[i];
    }
    if (threadIdx.x < NB) sB3[threadIdx.x] = b3[threadIdx.x];
    __syncthreads();

    const uint32_t aW0 = (uint32_t)__cvta_generic_to_shared(sW0);
    const uint32_t aB0 = (uint32_t)__cvta_generic_to_shared(sB0);
    const uint32_t aW1 = (uint32_t)__cvta_generic_to_shared(sW1);
    const uint32_t aB1 = (uint32_t)__cvta_generic_to_shared(sB1);
    const uint32_t aW2 = (uint32_t)__cvta_generic_to_shared(sW2);
    const uint32_t aB2 = (uint32_t)__cvta_generic_to_shared(sB2);
    const uint32_t aW3 = (uint32_t)__cvta_generic_to_shared(sW3);

    int t = blockIdx.x * TPB + threadIdx.x;   // 2 points per thread
    const float* xp = x + (long)t * 6;
    // keep x as 6 scalars; splat per-branch (ALU is idle)
    float xa0 = xp[0], xa1 = xp[1], xa2 = xp[2];
    float xb0 = xp[3], xb1 = xp[4], xb2 = xp[5];

    #pragma unroll 1
    for (int b = 0; b < NB; b++) {
        u64 accA[HD / 2], accB[HD / 2];
        float hA[HD], hB[HD];

        // ---- layer 0: 3 -> 32 ----
        {
            uint32_t wb = aW0 + b * 3 * HD * 4;
            uint32_t bb = aB0 + b * HD * 4;
            #pragma unroll
            for (int jp = 0; jp < HD / 2; jp++) {
                u64 bias = lds64(bb + jp * 8);
                accA[jp] = bias; accB[jp] = bias;
            }
            #pragma unroll
            for (int d = 0; d < 3; d++) {
                u64 xa = splat2((d == 0) ? xa0 : (d == 1) ? xa1 : xa2);
                u64 xb = splat2((d == 0) ? xb0 : (d == 1) ? xb1 : xb2);
                #pragma unroll
                for (int q = 0; q < HD / 4; q++) {
                    u64 w01, w23;
                    lds128(w01, w23, wb + d * HD * 4 + q * 16);
                    accA[2*q]   = ffma2(xa, w01, accA[2*q]);
                    accB[2*q]   = ffma2(xb, w01, accB[2*q]);
                    accA[2*q+1] = ffma2(xa, w23, accA[2*q+1]);
                    accB[2*q+1] = ffma2(xb, w23, accB[2*q+1]);
                }
            }
            #pragma unroll
            for (int jp = 0; jp < HD / 2; jp++) {
                float p, q2; unpk2(accA[jp], p, q2);
                hA[2*jp] = tanh_fast(p); hA[2*jp+1] = tanh_fast(q2);
                unpk2(accB[jp], p, q2);
                hB[2*jp] = tanh_fast(p); hB[2*jp+1] = tanh_fast(q2);
            }
        }

        // ---- layers 1 & 2: 32 -> 32 ----
        #pragma unroll 1
        for (int L = 0; L < 2; L++) {
            uint32_t wb = (L == 0 ? aW1 : aW2) + b * HD * HD * 4;
            uint32_t bb = (L == 0 ? aB1 : aB2) + b * HD * 4;
            #pragma unroll
            for (int jp = 0; jp < HD / 2; jp++) {
                u64 bias = lds64(bb + jp * 8);
                accA[jp] = bias; accB[jp] = bias;
            }
            #pragma unroll
            for (int d = 0; d < HD; d++) {
                u64 ha = splat2(hA[d]);
                u64 hb = splat2(hB[d]);
                #pragma unroll
                for (int q = 0; q < HD / 4; q++) {
                    u64 w01, w23;
                    lds128(w01, w23, wb + d * HD * 4 + q * 16);
                    accA[2*q]   = ffma2(ha, w01, accA[2*q]);
                    accB[2*q]   = ffma2(hb, w01, accB[2*q]);
                    accA[2*q+1] = ffma2(ha, w23, accA[2*q+1]);
                    accB[2*q+1] = ffma2(hb, w23, accB[2*q+1]);
                }
            }
            #pragma unroll
            for (int jp = 0; jp < HD / 2; jp++) {
                float p, q2; unpk2(accA[jp], p, q2);
                hA[2*jp] = tanh_fast(p); hA[2*jp+1] = tanh_fast(q2);
                unpk2(accB[jp], p, q2);
                hB[2*jp] = tanh_fast(p); hB[2*jp+1] = tanh_fast(q2);
            }
        }

        // ---- layer 3: 32 -> 1 (vector weight loads, scalar reductions) ----
        {
            uint32_t wb = aW3 + b * HD * 4;
            float sA = sB3[b], sBv = sA;
            #pragma unroll
            for (int q = 0; q < HD / 4; q++) {
                float w0, w1, w2, w3v;
                lds128f(w0, w1, w2, w3v, wb + q * 16);
                sA  = fmaf(hA[4*q+0], w0, sA);   sBv = fmaf(hB[4*q+0], w0, sBv);
                sA  = fmaf(hA[4*q+1], w1, sA);   sBv = fmaf(hB[4*q+1], w1, sBv);
                sA  = fmaf(hA[4*q+2], w2, sA);   sBv = fmaf(hB[4*q+2], w2, sBv);
                sA  = fmaf(hA[4*q+3], w3v, sA);  sBv = fmaf(hB[4*q+3], w3v, sBv);
            }
            // direct store: out is [N,4] row-major; points 2t and 2t+1, column b
            out[(long)(2 * t) * NB + b]     = sA;
            out[(long)(2 * t + 1) * NB + b] = sBv;
        }
    }
}

extern "C" void kernel_launch(void* const* d_in, const int* in_sizes, int n_in,
                              void* d_out, int out_size) {
    const float* x  = (const float*)d_in[0];
    const float* W0 = (const float*)d_in[1];
    const float* b0 = (const float*)d_in[2];
    const float* W1 = (const float*)d_in[3];
    const float* b1 = (const float*)d_in[4];
    const float* W2 = (const float*)d_in[5];
    const float* b2 = (const float*)d_in[6];
    const float* W3 = (const float*)d_in[7];
    const float* b3 = (const float*)d_in[8];
    float* out = (float*)d_out;

    int grid = (NPTS / 2) / TPB;   // 4096
    pfnn_kernel<<<grid, TPB>>>(x, W0, b0, W1, b1, W2, b2, W3, b3, out);
}

// round 13
// speedup vs baseline: 1.9815x; 1.9815x over previous
#include <cuda_runtime.h>
#include <cuda_fp16.h>
#include <cstdint>

#define NPTS 1048576
#define HD 32
#define NB 4
#define TPB 128
#define NTILES (NPTS / TPB)    // 8192 tiles of 128 points

// mma.sync.m16n8k16 row.col f32.f16.f16.f32 — baseline PTX, no 'a' feature needed.
#define MMA16816(C, A, B0, B1) \
    asm volatile("mma.sync.aligned.m16n8k16.row.col.f32.f16.f16.f32 " \
                 "{%0,%1,%2,%3}, {%4,%5,%6,%7}, {%8,%9}, {%0,%1,%2,%3};" \
                 : "+f"((C)[0]), "+f"((C)[1]), "+f"((C)[2]), "+f"((C)[3]) \
                 : "r"((A)[0]), "r"((A)[1]), "r"((A)[2]), "r"((A)[3]), \
                   "r"((B0)), "r"((B1)))

__device__ __forceinline__ float tanh_fast(float x) {
    float y; asm("tanh.approx.f32 %0, %1;" : "=f"(y) : "f"(x));
    return y;
}
// pack two f32 -> f16x2 (lo = v0), and the f16 residuals (lo-split)
__device__ __forceinline__ void split_pack(float v0, float v1, uint32_t& hi, uint32_t& lo) {
    __half2 hh = __floats2half2_rn(v0, v1);      // .x = v0 (low half)
    float2 back = __half22float2(hh);
    __half2 hl = __floats2half2_rn(v0 - back.x, v1 - back.y);
    hi = *reinterpret_cast<uint32_t*>(&hh);
    lo = *reinterpret_cast<uint32_t*>(&hl);
}

// Fragment geometry (m16n8k16), lane = g*4+tg:
//  A: a0=(row g,   k 2tg,2tg+1)  a1=(row g+8, k 2tg,2tg+1)
//     a2=(row g,   k 2tg+8,+9)   a3=(row g+8, k 2tg+8,+9)
//  B: b0=(k 2tg,2tg+1, col g)    b1=(k 2tg+8,+9, col g)
//  C: c0,c1=(row g, col 2tg,+1)  c2,c3=(row g+8, col 2tg,+1)
// Chaining: next-layer A k-chunk0 <- C tiles j=0,1 ; k-chunk1 <- j=2,3 (in-thread).

__global__ __launch_bounds__(TPB, 3)
void pfnn_mma_kernel(const float* __restrict__ x,
                     const float* __restrict__ W0, const float* __restrict__ b0,
                     const float* __restrict__ W1, const float* __restrict__ b1,
                     const float* __restrict__ W2, const float* __restrict__ b2,
                     const float* __restrict__ W3, const float* __restrict__ b3,
                     float* __restrict__ out) {
    // Per-lane precomputed B fragments: fragIdx = (((l*4+br)*4+j)*2+c)*2+s
    // (l=layer, br=branch, j=n-tile, c=k-chunk, s=hi/lo split), 2 u32 words/lane.
    __shared__ uint32_t sBfrag[128 * 64];        // 32 KB
    __shared__ float sW0[NB * 3 * HD];
    __shared__ float sB0[NB * HD];
    __shared__ float sBias[2][NB * HD];          // b1, b2
    __shared__ float sW3[NB * HD];
    __shared__ float sB3v[NB];

    const int tid = threadIdx.x;
    const int lane = tid & 31;
    const int warp = tid >> 5;
    const int g = lane >> 2, tg = lane & 3;

    // ---- one-time prep: split W1/W2 into per-lane fp16 hi/lo B fragments ----
    for (int i = tid; i < 128 * 64; i += TPB) {
        int w = i & 1, ln = (i >> 1) & 31, f = i >> 6;
        int s = f & 1, c = (f >> 1) & 1, j = (f >> 2) & 3, br = (f >> 4) & 3, l = f >> 6;
        int ltg = ln & 3, lg = ln >> 2;
        int k0 = c * 16 + ltg * 2 + w * 8;
        int n  = j * 8 + lg;
        const float* W = (l ? W2 : W1) + br * HD * HD;
        float f0 = W[k0 * HD + n];
        float f1 = W[(k0 + 1) * HD + n];
        __half h0h = __float2half_rn(f0), h1h = __float2half_rn(f1);
        __half h0 = s ? __float2half_rn(f0 - __half2float(h0h)) : h0h;
        __half h1 = s ? __float2half_rn(f1 - __half2float(h1h)) : h1h;
        __half2 p = __halves2half2(h0, h1);      // lo = h0
        sBfrag[i] = *reinterpret_cast<uint32_t*>(&p);
    }
    for (int i = tid; i < NB * 3 * HD; i += TPB) sW0[i] = W0[i];
    for (int i = tid; i < NB * HD; i += TPB) {
        sB0[i] = b0[i];
        sBias[0][i] = b1[i];
        sBias[1][i] = b2[i];
        sW3[i] = W3[i];
    }
    if (tid < NB) sB3v[tid] = b3[tid];
    __syncthreads();

    for (int tile = blockIdx.x; tile < NTILES; tile += gridDim.x) {
        const int wb = tile * TPB + warp * 32;   // this warp's 32 points
        // own point's x, then shuffle the 4 rows this thread's fragments need
        const float* xp = x + (long)(wb + lane) * 3;
        float mx0 = xp[0], mx1 = xp[1], mx2 = xp[2];
        float xr[4][3];
        #pragma unroll
        for (int s = 0; s < 4; s++) {
            int src = g + 8 * s;                 // rows g, g+8, g+16, g+24
            xr[s][0] = __shfl_sync(0xffffffffu, mx0, src);
            xr[s][1] = __shfl_sync(0xffffffffu, mx1, src);
            xr[s][2] = __shfl_sync(0xffffffffu, mx2, src);
        }

        #pragma unroll 1
        for (int br = 0; br < NB; br++) {
            uint32_t aHH[16], aHL[16];           // A frags: [tile2(2)][kchunk(2)][a0..a3]

            // ---- layer 0 (K=3): compute directly in A-fragment layout ----
            #pragma unroll
            for (int cc = 0; cc < 4; cc++) {     // 4 column groups of 2 cols
                int col = cc * 8 + tg * 2;
                float2 w0d0 = *(const float2*)&sW0[(br * 3 + 0) * HD + col];
                float2 w0d1 = *(const float2*)&sW0[(br * 3 + 1) * HD + col];
                float2 w0d2 = *(const float2*)&sW0[(br * 3 + 2) * HD + col];
                float2 bia  = *(const float2*)&sB0[br * HD + col];
                #pragma unroll
                for (int t2 = 0; t2 < 2; t2++) {
                    #pragma unroll
                    for (int rl = 0; rl < 2; rl++) {
                        const float* xv = xr[t2 * 2 + rl];
                        float v0 = bia.x, v1 = bia.y;
                        v0 = fmaf(xv[0], w0d0.x, v0);  v1 = fmaf(xv[0], w0d0.y, v1);
                        v0 = fmaf(xv[1], w0d1.x, v0);  v1 = fmaf(xv[1], w0d1.y, v1);
                        v0 = fmaf(xv[2], w0d2.x, v0);  v1 = fmaf(xv[2], w0d2.y, v1);
                        int idx = t2 * 8 + (cc >> 1) * 4 + (cc & 1) * 2 + rl;
                        split_pack(tanh_fast(v0), tanh_fast(v1), aHH[idx], aHL[idx]);
                    }
                }
            }

            // ---- layers 1 & 2 via MMA chain ----
            #pragma unroll
            for (int l = 0; l < 2; l++) {
                float acc[2][4][4];
                #pragma unroll
                for (int j = 0; j < 4; j++) {
                    float2 bia = *(const float2*)&sBias[l][br * HD + j * 8 + tg * 2];
                    #pragma unroll
                    for (int t2 = 0; t2 < 2; t2++) {
                        acc[t2][j][0] = bia.x; acc[t2][j][1] = bia.y;
                        acc[t2][j][2] = bia.x; acc[t2][j][3] = bia.y;
                    }
                }
                const int fbase = ((l * 4 + br) * 4) * 4;   // fragIdx of (l,br,j=0,c=0,s=0)
                #pragma unroll
                for (int j = 0; j < 4; j++) {
                    const uint32_t* fp = &sBfrag[(fbase + j * 4) * 64 + lane * 2];
                    uint2 Bc0s0 = *(const uint2*)(fp);        // c=0,s=0
                    uint2 Bc0s1 = *(const uint2*)(fp + 64);   // c=0,s=1
                    uint2 Bc1s0 = *(const uint2*)(fp + 128);  // c=1,s=0
                    uint2 Bc1s1 = *(const uint2*)(fp + 192);  // c=1,s=1
                    #pragma unroll
                    for (int t2 = 0; t2 < 2; t2++) {
                        const uint32_t* hh0 = &aHH[t2 * 8];
                        const uint32_t* hh1 = &aHH[t2 * 8 + 4];
                        const uint32_t* hl0 = &aHL[t2 * 8];
                        const uint32_t* hl1 = &aHL[t2 * 8 + 4];
                        MMA16816(acc[t2][j], hh0, Bc0s0.x, Bc0s0.y);
                        MMA16816(acc[t2][j], hh1, Bc1s0.x, Bc1s0.y);
                        MMA16816(acc[t2][j], hl0, Bc0s0.x, Bc0s0.y);
                        MMA16816(acc[t2][j], hl1, Bc1s0.x, Bc1s0.y);
                        MMA16816(acc[t2][j], hh0, Bc0s1.x, Bc0s1.y);
                        MMA16816(acc[t2][j], hh1, Bc1s1.x, Bc1s1.y);
                    }
                }
                // tanh epilogue
                #pragma unroll
                for (int t2 = 0; t2 < 2; t2++)
                    #pragma unroll
                    for (int j = 0; j < 4; j++)
                        #pragma unroll
                        for (int r = 0; r < 4; r++)
                            acc[t2][j][r] = tanh_fast(acc[t2][j][r]);

                if (l == 0) {
                    // repack C frags -> next A frags (FA-style identity, in-thread)
                    #pragma unroll
                    for (int t2 = 0; t2 < 2; t2++)
                        #pragma unroll
                        for (int j = 0; j < 4; j++) {
                            int idx = t2 * 8 + (j >> 1) * 4 + (j & 1) * 2;
                            split_pack(acc[t2][j][0], acc[t2][j][1], aHH[idx],     aHL[idx]);
                            split_pack(acc[t2][j][2], acc[t2][j][3], aHH[idx + 1], aHL[idx + 1]);
                        }
                } else {
                    // ---- layer 3: dot over 32 cols + quad reduce + store ----
                    #pragma unroll
                    for (int t2 = 0; t2 < 2; t2++) {
                        float p0 = 0.f, p1 = 0.f;
                        #pragma unroll
                        for (int j = 0; j < 4; j++) {
                            float2 w3p = *(const float2*)&sW3[br * HD + j * 8 + tg * 2];
                            p0 = fmaf(acc[t2][j][0], w3p.x, p0);
                            p0 = fmaf(acc[t2][j][1], w3p.y, p0);
                            p1 = fmaf(acc[t2][j][2], w3p.x, p1);
                            p1 = fmaf(acc[t2][j][3], w3p.y, p1);
                        }
                        p0 += __shfl_xor_sync(0xffffffffu, p0, 1);
                        p0 += __shfl_xor_sync(0xffffffffu, p0, 2);
                        p1 += __shfl_xor_sync(0xffffffffu, p1, 1);
                        p1 += __shfl_xor_sync(0xffffffffu, p1, 2);
                        if (tg == 0) {
                            float bv = sB3v[br];
                            out[(long)(wb + t2 * 16 + g) * NB + br]     = p0 + bv;
                            out[(long)(wb + t2 * 16 + 8 + g) * NB + br] = p1 + bv;
                        }
                    }
                }
            }
        }
    }
}

extern "C" void kernel_launch(void* const* d_in, const int* in_sizes, int n_in,
                              void* d_out, int out_size) {
    const float* x  = (const float*)d_in[0];
    const float* W0 = (const float*)d_in[1];
    const float* b0 = (const float*)d_in[2];
    const float* W1 = (const float*)d_in[3];
    const float* b1 = (const float*)d_in[4];
    const float* W2 = (const float*)d_in[5];
    const float* b2 = (const float*)d_in[6];
    const float* W3 = (const float*)d_in[7];
    const float* b3 = (const float*)d_in[8];
    float* out = (float*)d_out;

    int nsm = 148;
    cudaDeviceGetAttribute(&nsm, cudaDevAttrMultiProcessorCount, 0);
    int grid = 4 * nsm;                 // persistent-style stride loop over 8192 tiles
    if (grid > NTILES) grid = NTILES;
    pfnn_mma_kernel<<<grid, TPB>>>(x, W0, b0, W1, b1, W2, b2, W3, b3, out);
}